// round 5
// baseline (speedup 1.0000x reference)
#include <cuda_runtime.h>

// EMA over the innermost frames axis.
// input:         (16, 8, 256, 2048) fp32, frames contiguous
// initial_state: (16, 8, 256)       fp32
// weight:        (8, 256)           fp32   (clamped to [0,1])
// out:           (16, 8, 256, 2048) fp32
//
// One warp per (b, res, bin) row. Each lane owns 8 consecutive frames
// (two float4s at 2*lane, 2*lane+1) per 256-frame chunk -> only 8 warp scans
// per row (vs 16 in the R2 baseline), halving the serial SHFL latency chain.
// Depth-1 chunk prefetch keeps 2 LDG.128 in flight per warp; streaming
// cache hints (single-touch data).

#define EMA_N_FRAMES 2048
#define EMA_CHUNK_FRAMES 256
#define EMA_CHUNKS (EMA_N_FRAMES / EMA_CHUNK_FRAMES)   // 8
#define EMA_WARPS_PER_BLOCK 8
#define EMA_THREADS (EMA_WARPS_PER_BLOCK * 32)

__global__ __launch_bounds__(EMA_THREADS)
void ema_scan_kernel(const float* __restrict__ x,
                     const float* __restrict__ y0,
                     const float* __restrict__ wgt,
                     float* __restrict__ out,
                     int n_rows, int wgt_mod) {
    const int warp_id = blockIdx.x * EMA_WARPS_PER_BLOCK + (threadIdx.x >> 5);
    if (warp_id >= n_rows) return;            // grid divides evenly; whole warps only
    const int lane = threadIdx.x & 31;

    // per-row smoothing coefficient (uniform across the warp)
    float w = wgt[warp_id % wgt_mod];
    w = fminf(fmaxf(w, 0.0f), 1.0f);
    const float a  = 1.0f - w;
    const float a2 = a  * a;
    const float a3 = a2 * a;
    const float a4 = a2 * a2;
    const float a5 = a4 * a;
    const float a6 = a4 * a2;
    const float a7 = a4 * a3;
    const float a8 = a4 * a4;

    // a8^lane: decay across `lane` preceding 8-frame segments
    float a8_lane = 1.0f;
    {
        float p = a8, r = 1.0f;
        int e = lane;
        while (e) { if (e & 1) r *= p; p *= p; e >>= 1; }
        a8_lane = r;
    }
    // a^256 = a8^32: full-chunk decay for the carry
    float a_chunk;
    {
        float a16  = a8  * a8;
        float a32  = a16 * a16;
        float a64  = a32 * a32;
        float a128 = a64 * a64;
        a_chunk    = a128 * a128;
    }

    const float4* __restrict__ xr =
        reinterpret_cast<const float4*>(x + (size_t)warp_id * EMA_N_FRAMES);
    float4* __restrict__ yr =
        reinterpret_cast<float4*>(out + (size_t)warp_id * EMA_N_FRAMES);

    float carry = y0[warp_id];

    // depth-1 chunk prefetch: the next chunk's 2 LDG.128 issue before compute
    float4 b0 = __ldcs(&xr[2 * lane]);
    float4 b1 = __ldcs(&xr[2 * lane + 1]);

    #pragma unroll 4
    for (int c = 0; c < EMA_CHUNKS; ++c) {
        float4 n0 = make_float4(0.f, 0.f, 0.f, 0.f);
        float4 n1 = make_float4(0.f, 0.f, 0.f, 0.f);
        if (c + 1 < EMA_CHUNKS) {
            n0 = __ldcs(&xr[(c + 1) * 64 + 2 * lane]);
            n1 = __ldcs(&xr[(c + 1) * 64 + 2 * lane + 1]);
        }

        // serial 8-element recurrence with zero incoming state
        float t0 = w * b0.x;
        float t1 = fmaf(a, t0, w * b0.y);
        float t2 = fmaf(a, t1, w * b0.z);
        float t3 = fmaf(a, t2, w * b0.w);
        float t4 = fmaf(a, t3, w * b1.x);
        float t5 = fmaf(a, t4, w * b1.y);
        float t6 = fmaf(a, t5, w * b1.z);
        float t7 = fmaf(a, t6, w * b1.w);

        // inclusive warp scan of lane-segment tails (decay a^8 per segment)
        float s  = t7;
        float pw = a8;
        #pragma unroll
        for (int off = 1; off < 32; off <<= 1) {
            float up = __shfl_up_sync(0xffffffffu, s, off);
            if (lane >= off) s = fmaf(pw, up, s);
            pw = pw * pw;
        }

        // prefix entering this lane's segment: exclusive scan + decayed carry
        float excl = __shfl_up_sync(0xffffffffu, s, 1);
        float pref = (lane == 0) ? carry : fmaf(a8_lane, carry, excl);

        float4 o0, o1;
        o0.x = fmaf(a,  pref, t0);
        o0.y = fmaf(a2, pref, t1);
        o0.z = fmaf(a3, pref, t2);
        o0.w = fmaf(a4, pref, t3);
        o1.x = fmaf(a5, pref, t4);
        o1.y = fmaf(a6, pref, t5);
        o1.z = fmaf(a7, pref, t6);
        o1.w = fmaf(a8, pref, t7);
        __stcs(&yr[c * 64 + 2 * lane],     o0);
        __stcs(&yr[c * 64 + 2 * lane + 1], o1);

        // carry = y at last frame of this chunk
        float s31 = __shfl_sync(0xffffffffu, s, 31);
        carry = fmaf(a_chunk, carry, s31);

        b0 = n0;
        b1 = n1;
    }
}

extern "C" void kernel_launch(void* const* d_in, const int* in_sizes, int n_in,
                              void* d_out, int out_size) {
    const float* x   = (const float*)d_in[0];   // input  (B, R, N, F)
    const float* y0  = (const float*)d_in[1];   // initial_state (B, R, N)
    const float* wgt = (const float*)d_in[2];   // weight (R, N)
    float* out = (float*)d_out;

    const int n_rows  = in_sizes[1];            // B*R*N = 32768 rows
    const int wgt_mod = in_sizes[2];            // R*N   = 2048

    const int blocks = (n_rows + EMA_WARPS_PER_BLOCK - 1) / EMA_WARPS_PER_BLOCK;
    ema_scan_kernel<<<blocks, EMA_THREADS>>>(x, y0, wgt, out, n_rows, wgt_mod);
}

// round 6
// speedup vs baseline: 1.0169x; 1.0169x over previous
#include <cuda_runtime.h>

// EMA over the innermost frames axis.
// input:         (16, 8, 256, 2048) fp32, frames contiguous
// initial_state: (16, 8, 256)       fp32
// weight:        (8, 256)           fp32   (clamped to [0,1])
// out:           (16, 8, 256, 2048) fp32
//
// One warp per (b, res, bin) row. Each lane owns one CONTIGUOUS float4
// (4 frames) of each 128-frame chunk (perfect coalescing — R5's stride-2
// layout regressed via 2x L1tex wavefronts). 16 chunks per row.
// R6: software-pipeline depth 4 — buffers hold chunks c..c+3, prefetch
// c+4,c+5 while computing c,c+1 => 4 LDG.128 in flight per warp.
// Streaming cache hints: data is single-touch.

#define EMA_N_FRAMES 2048
#define EMA_CHUNKS   (EMA_N_FRAMES / 128)   // 16
#define EMA_WARPS_PER_BLOCK 8
#define EMA_THREADS (EMA_WARPS_PER_BLOCK * 32)

struct EmaCoef {
    float w, a, a2, a3, a4, a_chunk, a4_lane;
};

// Process one 128-frame chunk held as a per-lane float4. Returns new carry.
__device__ __forceinline__ float ema_chunk(float4 v, float4* __restrict__ dst,
                                           float carry, const EmaCoef& k,
                                           int lane) {
    // serial 4-element recurrence with zero incoming state
    float t0 = k.w * v.x;
    float t1 = fmaf(k.a, t0, k.w * v.y);
    float t2 = fmaf(k.a, t1, k.w * v.z);
    float t3 = fmaf(k.a, t2, k.w * v.w);

    // inclusive warp scan of lane-segment tails (decay a^4 per segment)
    float s  = t3;
    float pw = k.a4;
    #pragma unroll
    for (int off = 1; off < 32; off <<= 1) {
        float up = __shfl_up_sync(0xffffffffu, s, off);
        if (lane >= off) s = fmaf(pw, up, s);
        pw = pw * pw;
    }

    // prefix entering this lane's segment: exclusive scan + decayed carry
    float excl = __shfl_up_sync(0xffffffffu, s, 1);
    float pref = (lane == 0) ? carry : fmaf(k.a4_lane, carry, excl);

    float4 o;
    o.x = fmaf(k.a,  pref, t0);
    o.y = fmaf(k.a2, pref, t1);
    o.z = fmaf(k.a3, pref, t2);
    o.w = fmaf(k.a4, pref, t3);
    __stcs(dst, o);   // streaming store: single-touch

    float s31 = __shfl_sync(0xffffffffu, s, 31);
    return fmaf(k.a_chunk, carry, s31);
}

__global__ __launch_bounds__(EMA_THREADS)
void ema_scan_kernel(const float* __restrict__ x,
                     const float* __restrict__ y0,
                     const float* __restrict__ wgt,
                     float* __restrict__ out,
                     int n_rows, int wgt_mod) {
    const int warp_id = blockIdx.x * EMA_WARPS_PER_BLOCK + (threadIdx.x >> 5);
    if (warp_id >= n_rows) return;            // grid divides evenly; whole warps only
    const int lane = threadIdx.x & 31;

    // per-row smoothing coefficient (uniform across the warp)
    float w = wgt[warp_id % wgt_mod];
    w = fminf(fmaxf(w, 0.0f), 1.0f);

    EmaCoef k;
    k.w  = w;
    k.a  = 1.0f - w;
    k.a2 = k.a * k.a;
    k.a3 = k.a2 * k.a;
    k.a4 = k.a2 * k.a2;
    {
        float a8   = k.a4 * k.a4;
        float a16  = a8   * a8;
        float a32  = a16  * a16;
        float a64  = a32  * a32;
        k.a_chunk  = a64  * a64;      // a^128
    }
    // a4^lane (decay across `lane` preceding 4-element segments)
    {
        float p = k.a4, r = 1.0f;
        int e = lane;
        while (e) { if (e & 1) r *= p; p *= p; e >>= 1; }
        k.a4_lane = r;
    }

    const float4* __restrict__ xr =
        reinterpret_cast<const float4*>(x + (size_t)warp_id * EMA_N_FRAMES);
    float4* __restrict__ yr =
        reinterpret_cast<float4*>(out + (size_t)warp_id * EMA_N_FRAMES);

    float carry = y0[warp_id];

    // software pipeline, depth 4: buffers hold chunks c..c+3
    float4 b0 = __ldcs(&xr[0 * 32 + lane]);
    float4 b1 = __ldcs(&xr[1 * 32 + lane]);
    float4 b2 = __ldcs(&xr[2 * 32 + lane]);
    float4 b3 = __ldcs(&xr[3 * 32 + lane]);

    #pragma unroll
    for (int c = 0; c < EMA_CHUNKS; c += 2) {
        float4 n0 = make_float4(0.f, 0.f, 0.f, 0.f);
        float4 n1 = make_float4(0.f, 0.f, 0.f, 0.f);
        if (c + 4 < EMA_CHUNKS) {
            n0 = __ldcs(&xr[(c + 4) * 32 + lane]);
            n1 = __ldcs(&xr[(c + 5) * 32 + lane]);
        }
        carry = ema_chunk(b0, &yr[c * 32 + lane],       carry, k, lane);
        carry = ema_chunk(b1, &yr[(c + 1) * 32 + lane], carry, k, lane);
        b0 = b2;
        b1 = b3;
        b2 = n0;
        b3 = n1;
    }
}

extern "C" void kernel_launch(void* const* d_in, const int* in_sizes, int n_in,
                              void* d_out, int out_size) {
    const float* x   = (const float*)d_in[0];   // input  (B, R, N, F)
    const float* y0  = (const float*)d_in[1];   // initial_state (B, R, N)
    const float* wgt = (const float*)d_in[2];   // weight (R, N)
    float* out = (float*)d_out;

    const int n_rows  = in_sizes[1];            // B*R*N = 32768 rows
    const int wgt_mod = in_sizes[2];            // R*N   = 2048

    const int blocks = (n_rows + EMA_WARPS_PER_BLOCK - 1) / EMA_WARPS_PER_BLOCK;
    ema_scan_kernel<<<blocks, EMA_THREADS>>>(x, y0, wgt, out, n_rows, wgt_mod);
}